// round 8
// baseline (speedup 1.0000x reference)
#include <cuda_runtime.h>
#include <cuda_bf16.h>

// Problem: GeneratingReconstructionLoss
//   p:      (16, 256)        float32   (4096 elems)
//   y_pred: (16, 256, 32000) float32   (131,072,000 elems)
//   y_true: (256,)           int32     (JAX x64 disabled: int64 -> int32)
//   out = sum(p * ce) / 256,  ce[n,b] = logsumexp(y_pred[n,b,:]) - y_pred[n,b,y_true[b]]
//
// R5: 80.4us, DRAM=81.4% (6.45 TB/s), occ 94%, nothing else binding.
// R6/R7 change (still unmeasured — container infra failed twice; this is a
// straight re-bench): 320-thread CTAs -> 8000 float4 / 320 = exactly 25
// vec4/thread (eliminates the 31-vs-32-iteration ragged-warp penalty, a
// structural +2.4% CTA wall-time loss at 256 threads). unroll 5 keeps 5
// LDG.128 in flight. Fused deterministic last-CTA reduction retained.

#define VOCAB       32000
#define N_STEPS     16
#define BATCH_SZ    256
#define N_ROWS      (N_STEPS * BATCH_SZ)   // 4096
#define VEC_PER_ROW (VOCAB / 4)            // 8000
#define CTA_THREADS 320                    // 10 warps; 8000/320 = 25 exactly
#define N_WARPS     (CTA_THREADS / 32)

__device__ float        g_partials[N_ROWS];
__device__ unsigned int g_ticket = 0;

__global__ __launch_bounds__(CTA_THREADS)
void ce_fused_kernel(const float* __restrict__ p,
                     const float* __restrict__ y_pred,
                     const int* __restrict__ y_true,
                     float* __restrict__ out)
{
    const int row = blockIdx.x;                       // n*BATCH + b
    const float4* __restrict__ x4 =
        reinterpret_cast<const float4*>(y_pred + (size_t)row * VOCAB);

    // exactly 25 vec4 per thread; unroll 5 batches 5 LDG.128 for MLP
    float s0 = 0.0f, s1 = 0.0f;
    #pragma unroll 5
    for (int i = threadIdx.x; i < VEC_PER_ROW; i += CTA_THREADS) {
        float4 v = __ldcs(&x4[i]);   // streaming: read-once, 4x larger than L2
        s0 += __expf(v.x) + __expf(v.y);
        s1 += __expf(v.z) + __expf(v.w);
    }
    float s = s0 + s1;

    // thread 0: issue scalar tail loads early, before the reduction wait
    float p_row = 0.0f;
    float x_tgt = 0.0f;
    if (threadIdx.x == 0) {
        const int b = row & (BATCH_SZ - 1);
        int tgt = __ldg(&y_true[b]);
        if (tgt < 0) tgt = 0;                 // defensive: OOB -> rel_err, not IMA
        if (tgt >= VOCAB) tgt = VOCAB - 1;
        x_tgt = __ldg(&y_pred[(size_t)row * VOCAB + (size_t)tgt]);
        p_row = __ldg(&p[row]);
    }

    // intra-warp reduce
    #pragma unroll
    for (int o = 16; o > 0; o >>= 1)
        s += __shfl_xor_sync(0xffffffffu, s, o);

    __shared__ float warp_sums[N_WARPS];
    __shared__ bool  is_last;
    const int wid = threadIdx.x >> 5;
    const int lid = threadIdx.x & 31;
    if (lid == 0) warp_sums[wid] = s;
    __syncthreads();

    if (threadIdx.x == 0) {
        float tot = 0.0f;
        #pragma unroll
        for (int w = 0; w < N_WARPS; ++w) tot += warp_sums[w];
        const float ce = __logf(tot) - x_tgt;
        g_partials[row] = p_row * ce;

        __threadfence();  // make partial visible before taking a ticket
        unsigned int prev = atomicAdd(&g_ticket, 1u);
        is_last = (prev == (unsigned int)(gridDim.x - 1));
    }
    __syncthreads();

    if (is_last) {
        // last CTA: deterministic fixed-order reduction of all partials
        float r = 0.0f;
        #pragma unroll
        for (int i = threadIdx.x; i < N_ROWS; i += CTA_THREADS)
            r += g_partials[i];

        #pragma unroll
        for (int o = 16; o > 0; o >>= 1)
            r += __shfl_xor_sync(0xffffffffu, r, o);

        if (lid == 0) warp_sums[wid] = r;
        __syncthreads();

        if (threadIdx.x == 0) {
            float tot = 0.0f;
            #pragma unroll
            for (int w = 0; w < N_WARPS; ++w) tot += warp_sums[w];
            out[0] = tot * (1.0f / (float)BATCH_SZ);
            g_ticket = 0;   // reset for next graph replay
        }
    }
}

extern "C" void kernel_launch(void* const* d_in, const int* in_sizes, int n_in,
                              void* d_out, int out_size)
{
    // Identify inputs by element count (robust to metadata ordering):
    //   p: 4096, y_pred: 131072000, y_true: 256
    const float* p      = nullptr;
    const float* y_pred = nullptr;
    const int*   y_true = nullptr;
    for (int i = 0; i < n_in; ++i) {
        if (in_sizes[i] == N_ROWS)            p      = (const float*)d_in[i];
        else if (in_sizes[i] == BATCH_SZ)     y_true = (const int*)d_in[i];
        else                                  y_pred = (const float*)d_in[i];
    }
    float* out = (float*)d_out;

    ce_fused_kernel<<<N_ROWS, CTA_THREADS>>>(p, y_pred, y_true, out);
}

// round 10
// speedup vs baseline: 1.0107x; 1.0107x over previous
#include <cuda_runtime.h>
#include <cuda_bf16.h>

// Problem: GeneratingReconstructionLoss
//   p:      (16, 256)        float32   (4096 elems)
//   y_pred: (16, 256, 32000) float32   (131,072,000 elems)
//   y_true: (256,)           int32     (JAX x64 disabled: int64 -> int32)
//   out = sum(p * ce) / 256,  ce[n,b] = logsumexp(y_pred[n,b,:]) - y_pred[n,b,y_true[b]]
//
// History: R4/R5 256-thr = 80.2/80.4us (DRAM 81.4%); R8 320-thr = 81.5us
// (FALSIFIED: warp raggedness invisible under DRAM-queue saturation).
// R9 (never ran, infra): split each row across 2 CTAs (grid 8192, 64 KB/CTA)
// to halve the end-of-kernel drain-tail granularity. R10 fixes an R9 race:
// the finisher previously reconstructed the row total from its own atomicAdd
// return value, which can miss the peer's half under cross-CTA interleaving.
// Now: fenced rowsum add -> cnt add; the CTA seeing prev==1 re-reads the
// accumulated rowsum coherently at L2 (atomicAdd +0.0f). Commutative fp add
// -> bitwise deterministic regardless of arrival order.

#define VOCAB        32000
#define N_STEPS      16
#define BATCH_SZ     256
#define N_ROWS       (N_STEPS * BATCH_SZ)   // 4096
#define VEC_PER_ROW  (VOCAB / 4)            // 8000
#define VEC_PER_HALF (VEC_PER_ROW / 2)      // 4000
#define CTA_THREADS  256
#define N_WARPS      (CTA_THREADS / 32)

__device__ float        g_rowsum[N_ROWS];        // zero-init; reset each replay
__device__ unsigned int g_rowcnt[N_ROWS];        // zero-init; reset each replay
__device__ float        g_partials[N_ROWS];
__device__ unsigned int g_ticket = 0;

__global__ __launch_bounds__(CTA_THREADS)
void ce_fused_kernel(const float* __restrict__ p,
                     const float* __restrict__ y_pred,
                     const int* __restrict__ y_true,
                     float* __restrict__ out)
{
    const int row  = blockIdx.x >> 1;             // n*BATCH + b
    const int half = blockIdx.x & 1;
    const float4* __restrict__ x4 =
        reinterpret_cast<const float4*>(y_pred + (size_t)row * VOCAB)
        + half * VEC_PER_HALF;

    float s0 = 0.0f, s1 = 0.0f;
    #pragma unroll 4
    for (int i = threadIdx.x; i < VEC_PER_HALF; i += CTA_THREADS) {
        float4 v = __ldcs(&x4[i]);   // streaming: read-once, 4x larger than L2
        s0 += __expf(v.x) + __expf(v.y);
        s1 += __expf(v.z) + __expf(v.w);
    }
    float s = s0 + s1;

    // thread 0: issue scalar tail loads early, before the reduction wait
    float p_row = 0.0f;
    float x_tgt = 0.0f;
    if (threadIdx.x == 0) {
        const int b = row & (BATCH_SZ - 1);
        int tgt = __ldg(&y_true[b]);
        if (tgt < 0) tgt = 0;                 // defensive: OOB -> rel_err, not IMA
        if (tgt >= VOCAB) tgt = VOCAB - 1;
        x_tgt = __ldg(&y_pred[(size_t)row * VOCAB + (size_t)tgt]);
        p_row = __ldg(&p[row]);
    }

    // intra-warp reduce
    #pragma unroll
    for (int o = 16; o > 0; o >>= 1)
        s += __shfl_xor_sync(0xffffffffu, s, o);

    __shared__ float warp_sums[N_WARPS];
    __shared__ bool  is_last;
    const int wid = threadIdx.x >> 5;
    const int lid = threadIdx.x & 31;
    if (lid == 0) warp_sums[wid] = s;
    __syncthreads();

    if (threadIdx.x == 0) {
        float half_sum = 0.0f;
        #pragma unroll
        for (int w = 0; w < N_WARPS; ++w) half_sum += warp_sums[w];

        // accumulate this half's sum; fence so the add is visible before
        // the counter bump is
        atomicAdd(&g_rowsum[row], half_sum);
        __threadfence();
        unsigned int prev = atomicAdd(&g_rowcnt[row], 1u);

        is_last = false;
        if (prev == 1u) {
            // second arriver: both fenced rowsum adds are visible; coherent
            // L2-point read of the accumulated total (order-independent sum)
            const float tot = atomicAdd(&g_rowsum[row], 0.0f);
            const float ce  = __logf(tot) - x_tgt;
            g_partials[row] = p_row * ce;
            // reset per-row state for the next graph replay
            g_rowsum[row] = 0.0f;
            g_rowcnt[row] = 0u;
            __threadfence();  // partial + resets visible before ticket
            unsigned int t = atomicAdd(&g_ticket, 1u);
            is_last = (t == (unsigned int)(N_ROWS - 1));
        }
    }
    __syncthreads();

    if (is_last) {
        // last row-finisher: deterministic fixed-order reduction of partials
        float r = 0.0f;
        #pragma unroll
        for (int i = threadIdx.x; i < N_ROWS; i += CTA_THREADS)
            r += g_partials[i];

        #pragma unroll
        for (int o = 16; o > 0; o >>= 1)
            r += __shfl_xor_sync(0xffffffffu, r, o);

        if (lid == 0) warp_sums[wid] = r;
        __syncthreads();

        if (threadIdx.x == 0) {
            float tot = 0.0f;
            #pragma unroll
            for (int w = 0; w < N_WARPS; ++w) tot += warp_sums[w];
            out[0] = tot * (1.0f / (float)BATCH_SZ);
            g_ticket = 0;   // reset for next graph replay
        }
    }
}

extern "C" void kernel_launch(void* const* d_in, const int* in_sizes, int n_in,
                              void* d_out, int out_size)
{
    // Identify inputs by element count (robust to metadata ordering):
    //   p: 4096, y_pred: 131072000, y_true: 256
    const float* p      = nullptr;
    const float* y_pred = nullptr;
    const int*   y_true = nullptr;
    for (int i = 0; i < n_in; ++i) {
        if (in_sizes[i] == N_ROWS)            p      = (const float*)d_in[i];
        else if (in_sizes[i] == BATCH_SZ)     y_true = (const int*)d_in[i];
        else                                  y_pred = (const float*)d_in[i];
    }
    float* out = (float*)d_out;

    ce_fused_kernel<<<N_ROWS * 2, CTA_THREADS>>>(p, y_pred, y_true, out);
}